// round 14
// baseline (speedup 1.0000x reference)
#include <cuda_runtime.h>
#include <cuda_bf16.h>
#include <cstdint>

// Problem constants (fixed shapes from reference)
constexpr int B = 256;
constexpr int P = 1024;
constexpr int G = 128;
constexpr float DIST_T2 = 500.0f * 500.0f;   // compare squared distance
constexpr float BBOX_THRESH = 0.1f;
constexpr float SENTINEL = 1.0e15f;          // d2 ~ 3e30: finite, never ties/beats real

constexpr int THREADS = 128;                  // 1 proposal/thread
constexpr int PROPS_PER_CTA = THREADS;        // 128
constexpr int CHUNKS_PB = P / PROPS_PER_CTA;  // 8
constexpr int NTASKS = B * CHUNKS_PB;         // 2048

// Snake scheduling over rows of SM_ROW tasks. After sorting tasks by n
// descending, each row of SM_ROW consecutive ranks holds near-equal work;
// hardware round-robins consecutive bids across SMs, so every SM receives
// ~one task per row -> per-SM totals deterministically balanced. The last
// (smallest) tasks spill past wave-1 residency and are hardware-backfilled:
// LPT finishing.
constexpr int SM_ROW = 152;                   // GB300 SM count
constexpr int STATIC_BIDS = (NTASKS / SM_ROW) * SM_ROW;  // 1976 (13 rows)

__device__ int g_order[B];   // batches sorted by num_person descending

// Counting sort of 256 batches by n (1..128), descending. ~1us.
__global__ void order_kernel(const int* __restrict__ num_person) {
    __shared__ int hist[130];
    __shared__ int off[130];
    const int t = threadIdx.x;            // 256 threads == B
    if (t < 130) hist[t] = 0;
    __syncthreads();
    const int nb = num_person[t];
    atomicAdd(&hist[nb], 1);
    __syncthreads();
    if (t == 0) {
        int acc = 0;
        for (int v = 128; v >= 1; --v) { off[v] = acc; acc += hist[v]; }
    }
    __syncthreads();
    const int pos = atomicAdd(&off[nb], 1);
    g_order[pos] = t;                     // any order within equal n is valid
}

__device__ __forceinline__ uint64_t pack2(float lo, float hi) {
    uint64_t r;
    asm("mov.b64 %0, {%1, %2};" : "=l"(r) : "f"(lo), "f"(hi));
    return r;
}

// d2 for a GT pair, entirely inside one asm block so the packed temporaries
// never leak into C++ register allocation. Inputs pre-negated: d = p + (-g).
__device__ __forceinline__ void d2pair(uint64_t X2, uint64_t Y2, uint64_t Z2,
                                       uint64_t gnx, uint64_t gny, uint64_t gnz,
                                       float& a, float& b) {
    asm("{\n\t"
        ".reg .b64 dx, dy, dz, acc;\n\t"
        "add.rn.f32x2 dx, %2, %4;\n\t"
        "add.rn.f32x2 dy, %3, %5;\n\t"
        "add.rn.f32x2 dz, %6, %7;\n\t"
        "mul.rn.f32x2 acc, dz, dz;\n\t"
        "fma.rn.f32x2 acc, dy, dy, acc;\n\t"
        "fma.rn.f32x2 acc, dx, dx, acc;\n\t"
        "mov.b64 {%0, %1}, acc;\n\t"
        "}"
        : "=f"(a), "=f"(b)
        : "l"(X2), "l"(Y2), "l"(gnx), "l"(gny), "l"(Z2), "l"(gnz));
}

__global__ __launch_bounds__(THREADS) void proposal_kernel(
    const float* __restrict__ topk_index,    // [B,P,3]
    const float* __restrict__ topk_confs,    // [B,P]
    const float* __restrict__ bbox_preds,    // [B,P,2]
    const float* __restrict__ gt_3d,         // [B,G,3]
    const float* __restrict__ gt_bbox,       // [B,G,2]
    const int*   __restrict__ num_person,    // [B]
    float*       __restrict__ out)           // [B,P,7]
{
    __shared__ ulonglong2 sxy[G / 2];
    __shared__ ulonglong2 szz[G / 4];

    const int tid = threadIdx.x;
    const int bid = blockIdx.x;

    // bid -> rank: snake over 13 full rows of SM_ROW; remainder = identity
    // (smallest tasks, dynamically backfilled past wave-1 residency).
    int rank;
    if (bid < STATIC_BIDS) {
        const int row = bid / SM_ROW;
        const int c   = bid - row * SM_ROW;
        rank = row * SM_ROW + ((row & 1) ? (SM_ROW - 1 - c) : c);
    } else {
        rank = bid;
    }
    const int b     = g_order[rank >> 3];     // sorted-desc batch
    const int chunk = rank & 7;
    const int n     = num_person[b];          // uniform per CTA

    // Stage GT negated (tid == g). Slots g >= n get the sentinel so the
    // padded, remainder-free loop is exact: real slots come first (n >= 1),
    // max real d2 ~ 1.92e8 << sentinel d2 ~ 3e30 (never ties, never wins).
    {
        float ngx = -SENTINEL, ngy = -SENTINEL, ngz = -SENTINEL;
        if (tid < n) {
            const float* g3 = gt_3d + ((size_t)b * G + tid) * 3;
            ngx = -g3[0]; ngy = -g3[1]; ngz = -g3[2];
        }
        float* fxy = reinterpret_cast<float*>(sxy);
        fxy[(tid >> 1) * 4 + (tid & 1)]     = ngx;   // x lane of pair tid>>1
        fxy[(tid >> 1) * 4 + 2 + (tid & 1)] = ngy;   // y lane
        reinterpret_cast<float*>(szz)[tid]  = ngz;   // z lanes, 4 per record
    }
    __syncthreads();

    const int    p  = chunk * PROPS_PER_CTA + tid;
    const size_t bp = (size_t)b * P + p;

    const float x = topk_index[bp * 3 + 0];
    const float y = topk_index[bp * 3 + 1];
    const float z = topk_index[bp * 3 + 2];

    // Hoist per-proposal gmem loads so their latency overlaps the loop.
    const float q0 = bbox_preds[bp * 2 + 0];
    const float q1 = bbox_preds[bp * 2 + 1];
    const float cf = topk_confs[bp];

    const uint64_t X2 = pack2(x, x);
    const uint64_t Y2 = pack2(y, y);
    const uint64_t Z2 = pack2(z, z);

    // 4 champions, one per residue class g mod 4. FSETP off-chain; carried
    // deps are only the 4-cycle FMNMX (best) and SEL (idx).
    float b0 = 3.402823466e38f, b1 = 3.402823466e38f;
    float b2 = 3.402823466e38f, b3 = 3.402823466e38f;
    int   i0 = 0, i1 = 0, i2 = 0, i3 = 0;

    const int nsteps = ((n + 7) & ~7) >> 2;   // 4 GT per step, no remainder
    #pragma unroll 2
    for (int k = 0; k < nsteps; ++k) {
        const ulonglong2 A0 = sxy[2 * k];      // pairs 2k   : LDS.128
        const ulonglong2 A1 = sxy[2 * k + 1];  // pairs 2k+1 : LDS.128
        const ulonglong2 Zk = szz[k];          // both z-pairs: LDS.128

        float d0a, d0b, d1a, d1b;
        d2pair(X2, Y2, Z2, A0.x, A0.y, Zk.x, d0a, d0b);  // g = 4k, 4k+1
        d2pair(X2, Y2, Z2, A1.x, A1.y, Zk.y, d1a, d1b);  // g = 4k+2, 4k+3

        const bool c0 = d0a < b0;
        const bool c1 = d0b < b1;
        const bool c2 = d1a < b2;
        const bool c3 = d1b < b3;
        b0 = fminf(b0, d0a);  i0 = c0 ? k : i0;
        b1 = fminf(b1, d0b);  i1 = c1 ? k : i1;
        b2 = fminf(b2, d1a);  i2 = c2 ? k : i2;
        b3 = fminf(b3, d1b);  i3 = c3 ? k : i3;
    }

    // Exact first-index merge: lexicographic (d2, global index). Strict <
    // within each residue plus index tie-break across residues reproduces
    // JAX argmin's first-index semantics exactly.
    int   g0 = 4 * i0, g1 = 4 * i1 + 1, g2 = 4 * i2 + 2, g3 = 4 * i3 + 3;
    float ba = b0; int ga = g0;
    if ((b1 < ba) || (b1 == ba && g1 < ga)) { ba = b1; ga = g1; }
    if ((b2 < ba) || (b2 == ba && g2 < ga)) { ba = b2; ga = g2; }
    if ((b3 < ba) || (b3 == ba && g3 < ga)) { ba = b3; ga = g3; }

    // dist > 500  <=>  d2 > 500^2 (sqrt monotone; compare-exact)
    const float p2g = (ba > DIST_T2) ? -1.0f : (float)ga;

    // Matched GT bbox: one divergent LDG.64 (L2-hot), no smem staging.
    const float2 mb = reinterpret_cast<const float2*>(gt_bbox)[(size_t)b * G + ga];
    const bool cond = (p2g >= 0.0f) &&
                      ((q0 < mb.x - BBOX_THRESH) || (q1 < mb.y - BBOX_THRESH));

    // Direct 7-float store (contiguous 28B per thread, 3.5KB per CTA tile).
    float* o = out + bp * 7;
    o[0] = x;  o[1] = y;  o[2] = z;
    o[3] = p2g; o[4] = cf;
    o[5] = cond ? mb.x : q0;
    o[6] = cond ? mb.y : q1;
}

extern "C" void kernel_launch(void* const* d_in, const int* in_sizes, int n_in,
                              void* d_out, int out_size) {
    const float* topk_index  = (const float*)d_in[0];  // [B,P,3]
    const float* topk_confs  = (const float*)d_in[1];  // [B,P]
    const float* bbox_preds  = (const float*)d_in[2];  // [B,P,2]
    const float* gt_3d       = (const float*)d_in[3];  // [B,G,3]
    const float* gt_bbox     = (const float*)d_in[4];  // [B,G,2]
    const int*   num_person  = (const int*)  d_in[5];  // [B]
    float*       out         = (float*)d_out;          // [B,P,7]

    order_kernel<<<1, B>>>(num_person);
    proposal_kernel<<<NTASKS, THREADS>>>(topk_index, topk_confs, bbox_preds,
                                         gt_3d, gt_bbox, num_person, out);
}

// round 15
// speedup vs baseline: 1.0104x; 1.0104x over previous
#include <cuda_runtime.h>
#include <cuda_bf16.h>

// Problem constants (fixed shapes from reference)
constexpr int B = 256;
constexpr int P = 1024;
constexpr int G = 128;
constexpr float DIST_T2 = 500.0f * 500.0f;   // compare squared distance
constexpr float BBOX_THRESH = 0.1f;
constexpr float SENTINEL = 1.0e15f;          // d2 ~ 3e30: finite, never ties/beats real

constexpr int THREADS = 256;                  // 256t CTAs: the high-issue regime
constexpr int PROPS_PER_CTA = THREADS;        // 1 proposal / thread
constexpr int CHUNKS_PB = P / PROPS_PER_CTA;  // 4
constexpr int NCTAS = B * CHUNKS_PB;          // 1024

// Scalar d2 (exact: identical op/rounding sequence to the reference path
// used by every passing round; sqrt elided since compares are monotone).
__device__ __forceinline__ float d2f(float x, float y, float z, float4 g) {
    const float dx = x - g.x;
    const float dy = y - g.y;
    const float dz = z - g.z;
    return fmaf(dx, dx, fmaf(dy, dy, dz * dz));
}

__global__ __launch_bounds__(THREADS) void proposal_kernel(
    const float* __restrict__ topk_index,    // [B,P,3]
    const float* __restrict__ topk_confs,    // [B,P]
    const float* __restrict__ bbox_preds,    // [B,P,2]
    const float* __restrict__ gt_3d,         // [B,G,3]
    const float* __restrict__ gt_bbox,       // [B,G,2]
    const int*   __restrict__ num_person,    // [B]
    float*       __restrict__ out)           // [B,P,7]
{
    __shared__ float4 sgt[G];                 // (gx,gy,gz,pad): 1 LDS.128/GT

    const int tid   = threadIdx.x;
    const int b     = blockIdx.x >> 2;        // 4 chunks per batch
    const int chunk = blockIdx.x & 3;
    const int n     = num_person[b];          // uniform per CTA

    // Stage GT (tid == g for tid < 128). Slots g >= n get the sentinel so
    // the padded, remainder-free loop is exact: real slots come first
    // (n >= 1), max real d2 ~ 1.92e8 << sentinel d2 ~ 3e30.
    if (tid < G) {
        float4 v = make_float4(SENTINEL, SENTINEL, SENTINEL, 0.0f);
        if (tid < n) {
            const float* g3 = gt_3d + ((size_t)b * G + tid) * 3;
            v = make_float4(g3[0], g3[1], g3[2], 0.0f);
        }
        sgt[tid] = v;
    }
    __syncthreads();

    const int    p  = chunk * PROPS_PER_CTA + tid;
    const size_t bp = (size_t)b * P + p;

    const float x = topk_index[bp * 3 + 0];
    const float y = topk_index[bp * 3 + 1];
    const float z = topk_index[bp * 3 + 2];

    // Hoist per-proposal gmem loads so their latency overlaps the loop.
    const float q0 = bbox_preds[bp * 2 + 0];
    const float q1 = bbox_preds[bp * 2 + 1];
    const float cf = topk_confs[bp];

    // 4 champions, one per residue class g mod 4; index register holds the
    // step counter k (no per-slot IADD). FSETP off-chain; carried deps are
    // the 4-cycle FMNMX (best) and SEL (idx) only. All-scalar FFMA/FADD:
    // rt=2, clean RF banking (the f32x2 path stalled issue at 56-62%).
    float b0 = 3.402823466e38f, b1 = 3.402823466e38f;
    float b2 = 3.402823466e38f, b3 = 3.402823466e38f;
    int   i0 = 0, i1 = 0, i2 = 0, i3 = 0;

    const int nsteps = ((n + 7) & ~7) >> 2;   // 4 GT per step, even count
    #pragma unroll 2
    for (int k = 0; k < nsteps; ++k) {
        const float4 gA = sgt[4 * k + 0];     // broadcast LDS.128 x4
        const float4 gB = sgt[4 * k + 1];
        const float4 gC = sgt[4 * k + 2];
        const float4 gD = sgt[4 * k + 3];

        const float dA = d2f(x, y, z, gA);
        const float dB = d2f(x, y, z, gB);
        const float dC = d2f(x, y, z, gC);
        const float dD = d2f(x, y, z, gD);

        const bool c0 = dA < b0;
        const bool c1 = dB < b1;
        const bool c2 = dC < b2;
        const bool c3 = dD < b3;
        b0 = fminf(b0, dA);  i0 = c0 ? k : i0;
        b1 = fminf(b1, dB);  i1 = c1 ? k : i1;
        b2 = fminf(b2, dC);  i2 = c2 ? k : i2;
        b3 = fminf(b3, dD);  i3 = c3 ? k : i3;
    }

    // Exact first-index merge: lexicographic (d2, global index). Strict <
    // within each residue plus index tie-break across residues reproduces
    // JAX argmin's first-index semantics exactly.
    int   g0 = 4 * i0, g1 = 4 * i1 + 1, g2 = 4 * i2 + 2, g3 = 4 * i3 + 3;
    float ba = b0; int ga = g0;
    if ((b1 < ba) || (b1 == ba && g1 < ga)) { ba = b1; ga = g1; }
    if ((b2 < ba) || (b2 == ba && g2 < ga)) { ba = b2; ga = g2; }
    if ((b3 < ba) || (b3 == ba && g3 < ga)) { ba = b3; ga = g3; }

    // dist > 500  <=>  d2 > 500^2 (sqrt monotone; compare-exact)
    const float p2g = (ba > DIST_T2) ? -1.0f : (float)ga;

    // Matched GT bbox: one divergent LDG.64 (L2-hot), no smem staging.
    const float2 mb = reinterpret_cast<const float2*>(gt_bbox)[(size_t)b * G + ga];
    const bool cond = (p2g >= 0.0f) &&
                      ((q0 < mb.x - BBOX_THRESH) || (q1 < mb.y - BBOX_THRESH));

    // Direct 7-float store (contiguous 28B per thread, 7KB per CTA tile).
    float* o = out + bp * 7;
    o[0] = x;  o[1] = y;  o[2] = z;
    o[3] = p2g; o[4] = cf;
    o[5] = cond ? mb.x : q0;
    o[6] = cond ? mb.y : q1;
}

extern "C" void kernel_launch(void* const* d_in, const int* in_sizes, int n_in,
                              void* d_out, int out_size) {
    const float* topk_index  = (const float*)d_in[0];  // [B,P,3]
    const float* topk_confs  = (const float*)d_in[1];  // [B,P]
    const float* bbox_preds  = (const float*)d_in[2];  // [B,P,2]
    const float* gt_3d       = (const float*)d_in[3];  // [B,G,3]
    const float* gt_bbox     = (const float*)d_in[4];  // [B,G,2]
    const int*   num_person  = (const int*)  d_in[5];  // [B]
    float*       out         = (float*)d_out;          // [B,P,7]

    proposal_kernel<<<NCTAS, THREADS>>>(topk_index, topk_confs, bbox_preds,
                                        gt_3d, gt_bbox, num_person, out);
}

// round 16
// speedup vs baseline: 1.1916x; 1.1794x over previous
#include <cuda_runtime.h>
#include <cuda_bf16.h>
#include <cstdint>

// Problem constants (fixed shapes from reference)
constexpr int B = 256;
constexpr int P = 1024;
constexpr int G = 128;
constexpr float DIST_T2 = 500.0f * 500.0f;   // compare squared distance
constexpr float BBOX_THRESH = 0.1f;
constexpr float SENTINEL = 1.0e15f;          // d2 ~ 3e30: finite, never ties/beats real

constexpr int THREADS = 128;                  // 1 proposal/thread (R12 shape)
constexpr int PROPS_PER_CTA = THREADS;        // 128
constexpr int CHUNKS_PB = P / PROPS_PER_CTA;  // 8

__device__ __forceinline__ uint64_t pack2(float lo, float hi) {
    uint64_t r;
    asm("mov.b64 %0, {%1, %2};" : "=l"(r) : "f"(lo), "f"(hi));
    return r;
}

// d2 for a GT pair, entirely inside one asm block so the packed temporaries
// never leak into C++ register allocation. Inputs pre-negated: d = p + (-g).
// Deterministic: replaying with the same inputs gives bit-identical results.
__device__ __forceinline__ void d2pair(uint64_t X2, uint64_t Y2, uint64_t Z2,
                                       uint64_t gnx, uint64_t gny, uint64_t gnz,
                                       float& a, float& b) {
    asm("{\n\t"
        ".reg .b64 dx, dy, dz, acc;\n\t"
        "add.rn.f32x2 dx, %2, %4;\n\t"
        "add.rn.f32x2 dy, %3, %5;\n\t"
        "add.rn.f32x2 dz, %6, %7;\n\t"
        "mul.rn.f32x2 acc, dz, dz;\n\t"
        "fma.rn.f32x2 acc, dy, dy, acc;\n\t"
        "fma.rn.f32x2 acc, dx, dx, acc;\n\t"
        "mov.b64 {%0, %1}, acc;\n\t"
        "}"
        : "=f"(a), "=f"(b)
        : "l"(X2), "l"(Y2), "l"(gnx), "l"(gny), "l"(Z2), "l"(gnz));
}

__global__ __launch_bounds__(THREADS) void proposal_kernel(
    const float* __restrict__ topk_index,    // [B,P,3]
    const float* __restrict__ topk_confs,    // [B,P]
    const float* __restrict__ bbox_preds,    // [B,P,2]
    const float* __restrict__ gt_3d,         // [B,G,3]
    const float* __restrict__ gt_bbox,       // [B,G,2]
    const int*   __restrict__ num_person,    // [B]
    float*       __restrict__ out)           // [B,P,7]
{
    // Dense pair layout -> 3 x LDS.128 per 2 pairs (4 GT points):
    //   sxy[i] = ( (-gx_{2i},-gx_{2i+1}), (-gy_{2i},-gy_{2i+1}) )
    //   szz[k] = ( (-gz_{4k},-gz_{4k+1}), (-gz_{4k+2},-gz_{4k+3}) )
    __shared__ ulonglong2 sxy[G / 2];
    __shared__ ulonglong2 szz[G / 4];

    const int tid   = threadIdx.x;
    const int b     = blockIdx.x >> 3;        // 8 chunks per batch
    const int chunk = blockIdx.x & 7;
    const int n     = num_person[b];          // uniform per CTA

    // Stage GT negated (tid == g). Slots g >= n get the sentinel so the
    // padded, remainder-free loop is exact: real slots come first (n >= 1),
    // max real d2 ~ 1.92e8 << sentinel d2 ~ 3e30 (never ties, never wins).
    {
        float ngx = -SENTINEL, ngy = -SENTINEL, ngz = -SENTINEL;
        if (tid < n) {
            const float* g3 = gt_3d + ((size_t)b * G + tid) * 3;
            ngx = -g3[0]; ngy = -g3[1]; ngz = -g3[2];
        }
        float* fxy = reinterpret_cast<float*>(sxy);
        fxy[(tid >> 1) * 4 + (tid & 1)]     = ngx;   // x lane of pair tid>>1
        fxy[(tid >> 1) * 4 + 2 + (tid & 1)] = ngy;   // y lane
        reinterpret_cast<float*>(szz)[tid]  = ngz;   // z lanes, 4 per record
    }
    __syncthreads();

    const int    p  = chunk * PROPS_PER_CTA + tid;
    const size_t bp = (size_t)b * P + p;

    const float x = topk_index[bp * 3 + 0];
    const float y = topk_index[bp * 3 + 1];
    const float z = topk_index[bp * 3 + 2];

    // Hoist per-proposal gmem loads so their latency overlaps the loop.
    const float q0 = bbox_preds[bp * 2 + 0];
    const float q1 = bbox_preds[bp * 2 + 1];
    const float cf = topk_confs[bp];

    const uint64_t X2 = pack2(x, x);
    const uint64_t Y2 = pack2(y, y);
    const uint64_t Z2 = pack2(z, z);

    // Min-tree: reduce 4 distances/step to one scalar min (3 FMNMX), track a
    // single (best, step) champion (FSETP + FMNMX + SEL). Argmin index is
    // recovered after the loop by replaying the winning step (bit-exact).
    float best = 3.402823466e38f;
    int   kb   = 0;

    const int nsteps = ((n + 7) & ~7) >> 2;   // 4 GT per step, no remainder
    #pragma unroll 2
    for (int k = 0; k < nsteps; ++k) {
        const ulonglong2 A0 = sxy[2 * k];      // pairs 2k   : LDS.128
        const ulonglong2 A1 = sxy[2 * k + 1];  // pairs 2k+1 : LDS.128
        const ulonglong2 Zk = szz[k];          // both z-pairs: LDS.128

        float d0a, d0b, d1a, d1b;
        d2pair(X2, Y2, Z2, A0.x, A0.y, Zk.x, d0a, d0b);  // g = 4k, 4k+1
        d2pair(X2, Y2, Z2, A1.x, A1.y, Zk.y, d1a, d1b);  // g = 4k+2, 4k+3

        const float m01 = fminf(d0a, d0b);
        const float m23 = fminf(d1a, d1b);
        const float m   = fminf(m01, m23);

        const bool c = m < best;               // strict < -> first step wins
        best = fminf(best, m);
        kb   = c ? k : kb;
    }

    // Replay step kb (identical inputs -> bit-identical d2); the first lane
    // equal to best is the global first-index argmin:
    //   best is the global min; strict < made kb the FIRST step attaining
    //   it (any earlier equal value would have set kb earlier); within the
    //   step the first matching lane is the smallest index. == JAX argmin.
    int ga;
    {
        const ulonglong2 A0 = sxy[2 * kb];
        const ulonglong2 A1 = sxy[2 * kb + 1];
        const ulonglong2 Zk = szz[kb];
        float d0a, d0b, d1a, d1b;
        d2pair(X2, Y2, Z2, A0.x, A0.y, Zk.x, d0a, d0b);
        d2pair(X2, Y2, Z2, A1.x, A1.y, Zk.y, d1a, d1b);
        int j = 3;
        if      (d0a == best) j = 0;
        else if (d0b == best) j = 1;
        else if (d1a == best) j = 2;
        ga = 4 * kb + j;
    }

    // dist > 500  <=>  d2 > 500^2 (sqrt monotone; compare-exact)
    const float p2g = (best > DIST_T2) ? -1.0f : (float)ga;

    // Matched GT bbox: one divergent LDG.64 (L2-hot), no smem staging.
    const float2 mb = reinterpret_cast<const float2*>(gt_bbox)[(size_t)b * G + ga];
    const bool cond = (p2g >= 0.0f) &&
                      ((q0 < mb.x - BBOX_THRESH) || (q1 < mb.y - BBOX_THRESH));

    // Direct 7-float store (contiguous 28B per thread, 3.5KB per CTA tile).
    float* o = out + bp * 7;
    o[0] = x;  o[1] = y;  o[2] = z;
    o[3] = p2g; o[4] = cf;
    o[5] = cond ? mb.x : q0;
    o[6] = cond ? mb.y : q1;
}

extern "C" void kernel_launch(void* const* d_in, const int* in_sizes, int n_in,
                              void* d_out, int out_size) {
    const float* topk_index  = (const float*)d_in[0];  // [B,P,3]
    const float* topk_confs  = (const float*)d_in[1];  // [B,P]
    const float* bbox_preds  = (const float*)d_in[2];  // [B,P,2]
    const float* gt_3d       = (const float*)d_in[3];  // [B,G,3]
    const float* gt_bbox     = (const float*)d_in[4];  // [B,G,2]
    const int*   num_person  = (const int*)  d_in[5];  // [B]
    float*       out         = (float*)d_out;          // [B,P,7]

    proposal_kernel<<<B * CHUNKS_PB, THREADS>>>(topk_index, topk_confs, bbox_preds,
                                                gt_3d, gt_bbox, num_person, out);
}